// round 15
// baseline (speedup 1.0000x reference)
#include <cuda_runtime.h>
#include <cuda_fp16.h>
#include <cstdint>
#include <math.h>

#define GN_N_NODES 200000
#define GN_N_FEAT 256
#define NODES_PER_GEMV_BLOCK 32   // 8 warps x 4 nodes

// Scratch (device globals — zero-initialized BSS; no allocations allowed)
__device__ float  g_h[GN_N_NODES];      // x @ W
__device__ float  g_dis[GN_N_NODES];    // rsqrt(deg+1)
__device__ __half g_a[GN_N_NODES];      // fp16(dis * h) — gather source (400KB)
__device__ float  g_degacc[GN_N_NODES]; // edge-weight degree accumulator (kept zeroed)
__device__ int    g_is64;               // cached dtype verdict (written by k_fused1)

// ---------------------------------------------------------------------------
// Inline per-block dtype detection: warp 0 samples 32 spread int64 reads.
// Genuine int64 indices all land in [0, N); int32 data read as int64 pairs
// two indices -> out of range w.p. ~1 per sample. P(false verdict) ~ (1/N)^32.
// ---------------------------------------------------------------------------
__device__ __forceinline__ int detect_is64(const void* __restrict__ ei,
                                           int E, int N) {
    __shared__ int s;
    if (threadIdx.x < 32) {
        size_t stride = (size_t)(E / 32);
        long long v = ((const long long*)ei)[(size_t)threadIdx.x * stride];
        unsigned ok = __ballot_sync(0xFFFFFFFFu, v >= 0 && v < (long long)N);
        if (threadIdx.x == 0) s = (ok == 0xFFFFFFFFu) ? 1 : 0;
    }
    __syncthreads();
    return s;
}

// ---------------------------------------------------------------------------
// Fused kernel 1: GEMV blocks + degree-scatter blocks interleaved (Bresenham).
//   GEMV block: 8 warps × 4 nodes/warp:  h[n]=x[n,:]·W   (32 nodes/block)
//   DEG block : 256 thr × 8 edges:       degacc[col[e]] += attrs[e]
// Block 0 caches the dtype verdict for the later kernels.
// ---------------------------------------------------------------------------
__global__ void k_fused1(const float* __restrict__ x,
                         const float* __restrict__ W,
                         float* __restrict__ h,
                         float* __restrict__ degacc,
                         int n_nodes,
                         const void* __restrict__ ei,
                         const float* __restrict__ attrs,
                         int E,
                         int nb_gemv, int nb_total) {
    int is64 = detect_is64(ei, E, n_nodes);
    if (blockIdx.x == 0 && threadIdx.x == 0) g_is64 = is64;

    long long b = blockIdx.x;
    long long before = b * nb_gemv / nb_total;
    long long incl   = (b + 1) * nb_gemv / nb_total;
    if (incl > before) {
        // ---- GEMV block (id = before): 4 nodes per warp ----
        int warp = threadIdx.x >> 5;
        int lane = threadIdx.x & 31;
        int node0 = (int)before * NODES_PER_GEMV_BLOCK + warp * 4;

        const float4* wv = reinterpret_cast<const float4*>(W);
        float4 b0 = __ldg(&wv[lane]);
        float4 b1 = __ldg(&wv[lane + 32]);

#pragma unroll
        for (int k = 0; k < 4; k++) {
            int node = node0 + k;
            if (node >= n_nodes) break;
            const float4* xr = reinterpret_cast<const float4*>(x + (size_t)node * GN_N_FEAT);
            float4 a0 = __ldcs(&xr[lane]);
            float4 a1 = __ldcs(&xr[lane + 32]);
            float s = a0.x * b0.x + a0.y * b0.y + a0.z * b0.z + a0.w * b0.w
                    + a1.x * b1.x + a1.y * b1.y + a1.z * b1.z + a1.w * b1.w;
#pragma unroll
            for (int o = 16; o; o >>= 1) s += __shfl_down_sync(0xFFFFFFFFu, s, o);
            if (lane == 0) h[node] = s;
        }
    } else {
        // ---- DEG block (id = b - before), 8 edges/thread ----
        int did = (int)(b - before);
        long long e0 = ((long long)did * 256 + threadIdx.x) * 8;
        if (e0 >= E) return;
        if (e0 + 7 < E) {
            float4 w0 = __ldcs(reinterpret_cast<const float4*>(attrs + e0));
            float4 w1 = __ldcs(reinterpret_cast<const float4*>(attrs + e0 + 4));
            int c[8];
            if (is64) {
                const long long* p = (const long long*)ei + E;
#pragma unroll
                for (int j = 0; j < 4; j++) {
                    longlong2 cc = __ldcs(reinterpret_cast<const longlong2*>(p + e0 + 2 * j));
                    c[2 * j] = (int)cc.x; c[2 * j + 1] = (int)cc.y;
                }
            } else {
                const int* p = (const int*)ei + E;
                int4 ca = __ldcs(reinterpret_cast<const int4*>(p + e0));
                int4 cb = __ldcs(reinterpret_cast<const int4*>(p + e0 + 4));
                c[0] = ca.x; c[1] = ca.y; c[2] = ca.z; c[3] = ca.w;
                c[4] = cb.x; c[5] = cb.y; c[6] = cb.z; c[7] = cb.w;
            }
            atomicAdd(&degacc[c[0]], w0.x);
            atomicAdd(&degacc[c[1]], w0.y);
            atomicAdd(&degacc[c[2]], w0.z);
            atomicAdd(&degacc[c[3]], w0.w);
            atomicAdd(&degacc[c[4]], w1.x);
            atomicAdd(&degacc[c[5]], w1.y);
            atomicAdd(&degacc[c[6]], w1.z);
            atomicAdd(&degacc[c[7]], w1.w);
        } else {
            for (long long e = e0; e < E; e++) {
                int c = is64 ? (int)((const long long*)ei)[E + e]
                             : ((const int*)ei)[E + e];
                atomicAdd(&degacc[c], attrs[e]);
            }
        }
    }
}

// ---------------------------------------------------------------------------
// Kernel C (scalar — measured best): dis=rsqrt(deg+1); a=fp16(dis*h); out=0
// ---------------------------------------------------------------------------
__global__ void k_rsqrt(float* __restrict__ degacc,
                        float* __restrict__ dis,
                        const float* __restrict__ h,
                        __half* __restrict__ a,
                        float* __restrict__ out,
                        int n_nodes) {
    int i = blockIdx.x * blockDim.x + threadIdx.x;
    if (i < n_nodes) {
        float d = degacc[i] + 1.0f;
        degacc[i] = 0.0f;
        float di = rsqrtf(d);
        dis[i] = di;
        a[i]   = __float2half(di * h[i]);
        out[i] = 0.0f;
    }
}

// ---------------------------------------------------------------------------
// Kernel D: out[col] += a[row] * attrs   (4 edges/thread — measured best).
// Reads the cached dtype verdict (one L2-broadcast word, no per-block probe).
// ---------------------------------------------------------------------------
__global__ void k_msg(const void* __restrict__ ei,
                      const float* __restrict__ attrs,
                      const __half* __restrict__ a,
                      float* __restrict__ out,
                      int E) {
    int is64 = g_is64;
    long long e0 = ((long long)blockIdx.x * blockDim.x + threadIdx.x) * 4;
    if (e0 >= E) return;
    if (e0 + 3 < E) {
        float4 w = __ldcs(reinterpret_cast<const float4*>(attrs + e0));
        int r0, r1, r2, r3, c0, c1, c2, c3;
        if (is64) {
            const long long* pr = (const long long*)ei;
            const long long* pc = pr + E;
            longlong2 ra = __ldcs(reinterpret_cast<const longlong2*>(pr + e0));
            longlong2 rb = __ldcs(reinterpret_cast<const longlong2*>(pr + e0 + 2));
            longlong2 ca = __ldcs(reinterpret_cast<const longlong2*>(pc + e0));
            longlong2 cb = __ldcs(reinterpret_cast<const longlong2*>(pc + e0 + 2));
            r0 = (int)ra.x; r1 = (int)ra.y; r2 = (int)rb.x; r3 = (int)rb.y;
            c0 = (int)ca.x; c1 = (int)ca.y; c2 = (int)cb.x; c3 = (int)cb.y;
        } else {
            const int* pr = (const int*)ei;
            const int* pc = pr + E;
            int4 r = __ldcs(reinterpret_cast<const int4*>(pr + e0));
            int4 c = __ldcs(reinterpret_cast<const int4*>(pc + e0));
            r0 = r.x; r1 = r.y; r2 = r.z; r3 = r.w;
            c0 = c.x; c1 = c.y; c2 = c.z; c3 = c.w;
        }
        float v0 = __half2float(__ldg(&a[r0])) * w.x;
        float v1 = __half2float(__ldg(&a[r1])) * w.y;
        float v2 = __half2float(__ldg(&a[r2])) * w.z;
        float v3 = __half2float(__ldg(&a[r3])) * w.w;
        atomicAdd(&out[c0], v0);
        atomicAdd(&out[c1], v1);
        atomicAdd(&out[c2], v2);
        atomicAdd(&out[c3], v3);
    } else {
        for (long long e = e0; e < E; e++) {
            int r, c;
            if (is64) {
                r = (int)((const long long*)ei)[e];
                c = (int)((const long long*)ei)[E + e];
            } else {
                r = ((const int*)ei)[e];
                c = ((const int*)ei)[E + e];
            }
            atomicAdd(&out[c], __half2float(a[r]) * attrs[e]);
        }
    }
}

// ---------------------------------------------------------------------------
// Kernel E (scalar — measured best): out = Mish(dis*(out + dis*h) + b)
// ---------------------------------------------------------------------------
__global__ void k_finish(float* __restrict__ out,
                         const float* __restrict__ dis,
                         const float* __restrict__ h,
                         const float* __restrict__ b,
                         int n_nodes) {
    int i = blockIdx.x * blockDim.x + threadIdx.x;
    if (i < n_nodes) {
        float di = dis[i];
        float t = di * (out[i] + di * h[i]) + b[0];
        float sp = (t > 20.f) ? t : log1pf(expf(t));
        out[i] = t * tanhf(sp);
    }
}

extern "C" void kernel_launch(void* const* d_in, const int* in_sizes, int n_in,
                              void* d_out, int out_size) {
    // identify inputs by element count (descending: x > edge > attrs > W > b)
    int ix = 0, ie = 1, ia = 2, iw = 3, ib = 4;
    {
        long long best = -1;
        for (int i = 0; i < n_in; i++) if ((long long)in_sizes[i] > best) { best = in_sizes[i]; ix = i; }
        long long second = -1;
        for (int i = 0; i < n_in; i++) if (i != ix && (long long)in_sizes[i] > second) { second = in_sizes[i]; ie = i; }
        long long third = -1;
        for (int i = 0; i < n_in; i++) if (i != ix && i != ie && (long long)in_sizes[i] > third) { third = in_sizes[i]; ia = i; }
        long long fourth = -1;
        for (int i = 0; i < n_in; i++) if (i != ix && i != ie && i != ia && (long long)in_sizes[i] > fourth) { fourth = in_sizes[i]; iw = i; }
        for (int i = 0; i < n_in; i++) if (i != ix && i != ie && i != ia && i != iw) ib = i;
    }

    const float* x    = (const float*)d_in[ix];
    const void*  ei   = d_in[ie];
    const float* atts = (const float*)d_in[ia];
    const float* W    = (const float*)d_in[iw];
    const float* b    = (const float*)d_in[ib];
    float*       out  = (float*)d_out;

    const int E = in_sizes[ia];                 // 12.8M
    const int N = in_sizes[ix] / GN_N_FEAT;     // 200k

    float*  h;    cudaGetSymbolAddress((void**)&h,    g_h);
    float*  dis;  cudaGetSymbolAddress((void**)&dis,  g_dis);
    __half* a;    cudaGetSymbolAddress((void**)&a,    g_a);
    float*  dacc; cudaGetSymbolAddress((void**)&dacc, g_degacc);

    // 1: fused GEMV + degree scatter (interleaved; deg 8 edges/thread)
    {
        int nb_gemv = (N + NODES_PER_GEMV_BLOCK - 1) / NODES_PER_GEMV_BLOCK;
        int nb_deg  = (E + 2047) / 2048;
        int nb_total = nb_gemv + nb_deg;
        k_fused1<<<nb_total, 256>>>(x, W, h, dacc, N, ei, atts, E,
                                    nb_gemv, nb_total);
    }
    // 2: rsqrt + a = fp16(dis*h) + out init (scalar — measured best)
    k_rsqrt<<<(N + 255) / 256, 256>>>(dacc, dis, h, a, out, N);

    // 3: edge messages (4 edges/thread, fp16 gather, cached is64)
    {
        long long quads = ((long long)E + 3) / 4;
        int blocks = (int)((quads + 255) / 256);
        k_msg<<<blocks, 256>>>(ei, atts, a, out, E);
    }
    // 4: scale + self loop + bias + Mish (scalar — measured best)
    k_finish<<<(N + 255) / 256, 256>>>(out, dis, h, b, N);
}

// round 16
// speedup vs baseline: 1.0128x; 1.0128x over previous
#include <cuda_runtime.h>
#include <cuda_fp16.h>
#include <cstdint>
#include <math.h>

#define GN_N_NODES 200000
#define GN_N_FEAT 256
#define NODES_PER_GEMV_BLOCK 32   // 8 warps x 4 nodes

// Scratch (device globals — zero-initialized BSS; no allocations allowed)
__device__ float  g_h[GN_N_NODES];      // x @ W
__device__ float  g_dis[GN_N_NODES];    // rsqrt(deg+1)
__device__ __half g_a[GN_N_NODES];      // fp16(dis * h) — gather source (400KB)
__device__ float  g_degacc[GN_N_NODES]; // edge-weight degree accumulator (kept zeroed)
__device__ int    g_is64;               // cached dtype verdict (written by k_fused1)

// ---------------------------------------------------------------------------
// Inline per-block dtype detection: warp 0 samples 32 spread int64 reads.
// Genuine int64 indices all land in [0, N); int32 data read as int64 pairs
// two indices -> out of range w.p. ~1 per sample. P(false verdict) ~ (1/N)^32.
// ---------------------------------------------------------------------------
__device__ __forceinline__ int detect_is64(const void* __restrict__ ei,
                                           int E, int N) {
    __shared__ int s;
    if (threadIdx.x < 32) {
        size_t stride = (size_t)(E / 32);
        long long v = ((const long long*)ei)[(size_t)threadIdx.x * stride];
        unsigned ok = __ballot_sync(0xFFFFFFFFu, v >= 0 && v < (long long)N);
        if (threadIdx.x == 0) s = (ok == 0xFFFFFFFFu) ? 1 : 0;
    }
    __syncthreads();
    return s;
}

// ---------------------------------------------------------------------------
// Fused kernel 1: GEMV blocks + degree-scatter blocks interleaved (Bresenham).
//   GEMV block: 8 warps × 4 nodes/warp:  h[n]=x[n,:]·W   (32 nodes/block)
//   DEG block : 256 thr × 8 edges:       degacc[col[e]] += attrs[e]
// Block 0 caches the dtype verdict for the later kernels.
// ---------------------------------------------------------------------------
__global__ void k_fused1(const float* __restrict__ x,
                         const float* __restrict__ W,
                         float* __restrict__ h,
                         float* __restrict__ degacc,
                         int n_nodes,
                         const void* __restrict__ ei,
                         const float* __restrict__ attrs,
                         int E,
                         int nb_gemv, int nb_total) {
    int is64 = detect_is64(ei, E, n_nodes);
    if (blockIdx.x == 0 && threadIdx.x == 0) g_is64 = is64;

    long long b = blockIdx.x;
    long long before = b * nb_gemv / nb_total;
    long long incl   = (b + 1) * nb_gemv / nb_total;
    if (incl > before) {
        // ---- GEMV block (id = before): 4 nodes per warp ----
        int warp = threadIdx.x >> 5;
        int lane = threadIdx.x & 31;
        int node0 = (int)before * NODES_PER_GEMV_BLOCK + warp * 4;

        const float4* wv = reinterpret_cast<const float4*>(W);
        float4 b0 = __ldg(&wv[lane]);
        float4 b1 = __ldg(&wv[lane + 32]);

#pragma unroll
        for (int k = 0; k < 4; k++) {
            int node = node0 + k;
            if (node >= n_nodes) break;
            const float4* xr = reinterpret_cast<const float4*>(x + (size_t)node * GN_N_FEAT);
            float4 a0 = __ldcs(&xr[lane]);
            float4 a1 = __ldcs(&xr[lane + 32]);
            float s = a0.x * b0.x + a0.y * b0.y + a0.z * b0.z + a0.w * b0.w
                    + a1.x * b1.x + a1.y * b1.y + a1.z * b1.z + a1.w * b1.w;
#pragma unroll
            for (int o = 16; o; o >>= 1) s += __shfl_down_sync(0xFFFFFFFFu, s, o);
            if (lane == 0) h[node] = s;
        }
    } else {
        // ---- DEG block (id = b - before), 8 edges/thread ----
        int did = (int)(b - before);
        long long e0 = ((long long)did * 256 + threadIdx.x) * 8;
        if (e0 >= E) return;
        if (e0 + 7 < E) {
            float4 w0 = __ldcs(reinterpret_cast<const float4*>(attrs + e0));
            float4 w1 = __ldcs(reinterpret_cast<const float4*>(attrs + e0 + 4));
            int c[8];
            if (is64) {
                const long long* p = (const long long*)ei + E;
#pragma unroll
                for (int j = 0; j < 4; j++) {
                    longlong2 cc = __ldcs(reinterpret_cast<const longlong2*>(p + e0 + 2 * j));
                    c[2 * j] = (int)cc.x; c[2 * j + 1] = (int)cc.y;
                }
            } else {
                const int* p = (const int*)ei + E;
                int4 ca = __ldcs(reinterpret_cast<const int4*>(p + e0));
                int4 cb = __ldcs(reinterpret_cast<const int4*>(p + e0 + 4));
                c[0] = ca.x; c[1] = ca.y; c[2] = ca.z; c[3] = ca.w;
                c[4] = cb.x; c[5] = cb.y; c[6] = cb.z; c[7] = cb.w;
            }
            atomicAdd(&degacc[c[0]], w0.x);
            atomicAdd(&degacc[c[1]], w0.y);
            atomicAdd(&degacc[c[2]], w0.z);
            atomicAdd(&degacc[c[3]], w0.w);
            atomicAdd(&degacc[c[4]], w1.x);
            atomicAdd(&degacc[c[5]], w1.y);
            atomicAdd(&degacc[c[6]], w1.z);
            atomicAdd(&degacc[c[7]], w1.w);
        } else {
            for (long long e = e0; e < E; e++) {
                int c = is64 ? (int)((const long long*)ei)[E + e]
                             : ((const int*)ei)[E + e];
                atomicAdd(&degacc[c], attrs[e]);
            }
        }
    }
}

// ---------------------------------------------------------------------------
// Kernel C (vectorized 4 nodes/thread — R10 measured-best config):
//   dis = rsqrt(degacc+1) ; a = fp16(dis*h) ; out = 0 ; re-zero degacc
// ---------------------------------------------------------------------------
__global__ void k_rsqrt(float* __restrict__ degacc,
                        float* __restrict__ dis,
                        const float* __restrict__ h,
                        __half* __restrict__ a,
                        float* __restrict__ out,
                        int n_nodes) {
    int i = (blockIdx.x * blockDim.x + threadIdx.x) * 4;
    if (i + 3 < n_nodes) {
        float4 d = *reinterpret_cast<float4*>(degacc + i);
        float4 hv = *reinterpret_cast<const float4*>(h + i);
        float4 di;
        di.x = rsqrtf(d.x + 1.0f);
        di.y = rsqrtf(d.y + 1.0f);
        di.z = rsqrtf(d.z + 1.0f);
        di.w = rsqrtf(d.w + 1.0f);
        *reinterpret_cast<float4*>(dis + i) = di;
        *reinterpret_cast<float4*>(degacc + i) = make_float4(0.f, 0.f, 0.f, 0.f);
        *reinterpret_cast<float4*>(out + i)   = make_float4(0.f, 0.f, 0.f, 0.f);
        __half2* ap = reinterpret_cast<__half2*>(a + i);
        ap[0] = __floats2half2_rn(di.x * hv.x, di.y * hv.y);
        ap[1] = __floats2half2_rn(di.z * hv.z, di.w * hv.w);
    } else {
        for (int j = i; j < n_nodes; j++) {
            float dv = degacc[j] + 1.0f;
            degacc[j] = 0.0f;
            float div = rsqrtf(dv);
            dis[j] = div;
            a[j]   = __float2half(div * h[j]);
            out[j] = 0.0f;
        }
    }
}

// ---------------------------------------------------------------------------
// Kernel D: out[col] += a[row] * attrs   (4 edges/thread, 512-thread blocks).
// Reads the cached dtype verdict (one L2-broadcast word, no per-block probe).
// ---------------------------------------------------------------------------
__global__ void k_msg(const void* __restrict__ ei,
                      const float* __restrict__ attrs,
                      const __half* __restrict__ a,
                      float* __restrict__ out,
                      int E) {
    int is64 = g_is64;
    long long e0 = ((long long)blockIdx.x * blockDim.x + threadIdx.x) * 4;
    if (e0 >= E) return;
    if (e0 + 3 < E) {
        float4 w = __ldcs(reinterpret_cast<const float4*>(attrs + e0));
        int r0, r1, r2, r3, c0, c1, c2, c3;
        if (is64) {
            const long long* pr = (const long long*)ei;
            const long long* pc = pr + E;
            longlong2 ra = __ldcs(reinterpret_cast<const longlong2*>(pr + e0));
            longlong2 rb = __ldcs(reinterpret_cast<const longlong2*>(pr + e0 + 2));
            longlong2 ca = __ldcs(reinterpret_cast<const longlong2*>(pc + e0));
            longlong2 cb = __ldcs(reinterpret_cast<const longlong2*>(pc + e0 + 2));
            r0 = (int)ra.x; r1 = (int)ra.y; r2 = (int)rb.x; r3 = (int)rb.y;
            c0 = (int)ca.x; c1 = (int)ca.y; c2 = (int)cb.x; c3 = (int)cb.y;
        } else {
            const int* pr = (const int*)ei;
            const int* pc = pr + E;
            int4 r = __ldcs(reinterpret_cast<const int4*>(pr + e0));
            int4 c = __ldcs(reinterpret_cast<const int4*>(pc + e0));
            r0 = r.x; r1 = r.y; r2 = r.z; r3 = r.w;
            c0 = c.x; c1 = c.y; c2 = c.z; c3 = c.w;
        }
        float v0 = __half2float(__ldg(&a[r0])) * w.x;
        float v1 = __half2float(__ldg(&a[r1])) * w.y;
        float v2 = __half2float(__ldg(&a[r2])) * w.z;
        float v3 = __half2float(__ldg(&a[r3])) * w.w;
        atomicAdd(&out[c0], v0);
        atomicAdd(&out[c1], v1);
        atomicAdd(&out[c2], v2);
        atomicAdd(&out[c3], v3);
    } else {
        for (long long e = e0; e < E; e++) {
            int r, c;
            if (is64) {
                r = (int)((const long long*)ei)[e];
                c = (int)((const long long*)ei)[E + e];
            } else {
                r = ((const int*)ei)[e];
                c = ((const int*)ei)[E + e];
            }
            atomicAdd(&out[c], __half2float(a[r]) * attrs[e]);
        }
    }
}

// ---------------------------------------------------------------------------
// Kernel E (vectorized 4 nodes/thread — R10 measured-best config):
//   out = Mish(dis*(out + dis*h) + b)   (self-loop term in fp32)
// ---------------------------------------------------------------------------
__device__ __forceinline__ float mish_act(float t) {
    float sp = (t > 20.f) ? t : log1pf(expf(t));
    return t * tanhf(sp);
}

__global__ void k_finish(float* __restrict__ out,
                         const float* __restrict__ dis,
                         const float* __restrict__ h,
                         const float* __restrict__ b,
                         int n_nodes) {
    int i = (blockIdx.x * blockDim.x + threadIdx.x) * 4;
    float bv = b[0];
    if (i + 3 < n_nodes) {
        float4 o  = *reinterpret_cast<float4*>(out + i);
        float4 di = *reinterpret_cast<const float4*>(dis + i);
        float4 hv = *reinterpret_cast<const float4*>(h + i);
        o.x = mish_act(di.x * (o.x + di.x * hv.x) + bv);
        o.y = mish_act(di.y * (o.y + di.y * hv.y) + bv);
        o.z = mish_act(di.z * (o.z + di.z * hv.z) + bv);
        o.w = mish_act(di.w * (o.w + di.w * hv.w) + bv);
        *reinterpret_cast<float4*>(out + i) = o;
    } else {
        for (int j = i; j < n_nodes; j++) {
            float di = dis[j];
            out[j] = mish_act(di * (out[j] + di * h[j]) + bv);
        }
    }
}

extern "C" void kernel_launch(void* const* d_in, const int* in_sizes, int n_in,
                              void* d_out, int out_size) {
    // identify inputs by element count (descending: x > edge > attrs > W > b)
    int ix = 0, ie = 1, ia = 2, iw = 3, ib = 4;
    {
        long long best = -1;
        for (int i = 0; i < n_in; i++) if ((long long)in_sizes[i] > best) { best = in_sizes[i]; ix = i; }
        long long second = -1;
        for (int i = 0; i < n_in; i++) if (i != ix && (long long)in_sizes[i] > second) { second = in_sizes[i]; ie = i; }
        long long third = -1;
        for (int i = 0; i < n_in; i++) if (i != ix && i != ie && (long long)in_sizes[i] > third) { third = in_sizes[i]; ia = i; }
        long long fourth = -1;
        for (int i = 0; i < n_in; i++) if (i != ix && i != ie && i != ia && (long long)in_sizes[i] > fourth) { fourth = in_sizes[i]; iw = i; }
        for (int i = 0; i < n_in; i++) if (i != ix && i != ie && i != ia && i != iw) ib = i;
    }

    const float* x    = (const float*)d_in[ix];
    const void*  ei   = d_in[ie];
    const float* atts = (const float*)d_in[ia];
    const float* W    = (const float*)d_in[iw];
    const float* b    = (const float*)d_in[ib];
    float*       out  = (float*)d_out;

    const int E = in_sizes[ia];                 // 12.8M
    const int N = in_sizes[ix] / GN_N_FEAT;     // 200k

    float*  h;    cudaGetSymbolAddress((void**)&h,    g_h);
    float*  dis;  cudaGetSymbolAddress((void**)&dis,  g_dis);
    __half* a;    cudaGetSymbolAddress((void**)&a,    g_a);
    float*  dacc; cudaGetSymbolAddress((void**)&dacc, g_degacc);

    // 1: fused GEMV + degree scatter (interleaved; deg 8 edges/thread)
    {
        int nb_gemv = (N + NODES_PER_GEMV_BLOCK - 1) / NODES_PER_GEMV_BLOCK;
        int nb_deg  = (E + 2047) / 2048;
        int nb_total = nb_gemv + nb_deg;
        k_fused1<<<nb_total, 256>>>(x, W, h, dacc, N, ei, atts, E,
                                    nb_gemv, nb_total);
    }
    // 2: rsqrt + a = fp16(dis*h) + out init (4 nodes/thread)
    {
        int quads = (N + 3) / 4;
        k_rsqrt<<<(quads + 255) / 256, 256>>>(dacc, dis, h, a, out, N);
    }
    // 3: edge messages (4 edges/thread, fp16 gather, cached is64, 512 thr/blk)
    {
        long long quads = ((long long)E + 3) / 4;
        int blocks = (int)((quads + 511) / 512);
        k_msg<<<blocks, 512>>>(ei, atts, a, out, E);
    }
    // 4: scale + self loop + bias + Mish (4 nodes/thread)
    {
        int quads = (N + 3) / 4;
        k_finish<<<(quads + 255) / 256, 256>>>(out, dis, h, b, N);
    }
}